// round 7
// baseline (speedup 1.0000x reference)
#include <cuda_runtime.h>
#include <cuda_bf16.h>
#include <cstdint>

// ---------------------------------------------------------------------------
// Graph attention: QKV projections (mma.sync bf16 split GEMM, cp.async
// double-buffered B) + dst-sorted CSR (forked stream) + warp-per-node
// online softmax with software-pipelined edge loop.
// ---------------------------------------------------------------------------

#define HID 128
#define MAXN 100352           // 784 * 128, >= N
#define MAXE 1700000

__device__ float g_Q[(size_t)MAXN * HID];
__device__ float g_K[(size_t)MAXN * HID];
__device__ float g_V[(size_t)MAXN * HID];
__device__ __nv_bfloat16 g_wt_hi[3 * HID * HID];  // [mat][n][k] = W[k][n]
__device__ __nv_bfloat16 g_wt_lo[3 * HID * HID];
__device__ int   g_cnt[MAXN];
__device__ int   g_cursor[MAXN];
__device__ int   g_rowptr[MAXN + 1];
__device__ int   g_blksum[256];
__device__ int   g_ssrc[MAXE];

// ---------------------------------------------------------------------------
__device__ __forceinline__ uint32_t smem_u32(const void* p) {
    uint32_t a;
    asm("{ .reg .u64 t; cvta.to.shared.u64 t, %1; cvt.u32.u64 %0, t; }"
        : "=r"(a) : "l"(p));
    return a;
}
__device__ __forceinline__ void ldsm_x4(uint32_t* d, uint32_t addr) {
    asm volatile("ldmatrix.sync.aligned.m8n8.x4.shared.b16 {%0,%1,%2,%3}, [%4];"
                 : "=r"(d[0]), "=r"(d[1]), "=r"(d[2]), "=r"(d[3]) : "r"(addr));
}
__device__ __forceinline__ void mma_bf16(float* c, const uint32_t* a,
                                         uint32_t b0, uint32_t b1) {
    asm volatile("mma.sync.aligned.m16n8k16.row.col.f32.bf16.bf16.f32 "
                 "{%0,%1,%2,%3}, {%4,%5,%6,%7}, {%8,%9}, {%0,%1,%2,%3};"
                 : "+f"(c[0]), "+f"(c[1]), "+f"(c[2]), "+f"(c[3])
                 : "r"(a[0]), "r"(a[1]), "r"(a[2]), "r"(a[3]),
                   "r"(b0), "r"(b1));
}
__device__ __forceinline__ uint32_t bf2_bits(float x, float y) {
    __nv_bfloat162 t(__float2bfloat16_rn(x), __float2bfloat16_rn(y));
    return *reinterpret_cast<uint32_t*>(&t);
}
__device__ __forceinline__ void cp16(uint32_t smem_dst, const void* gsrc) {
    asm volatile("cp.async.cg.shared.global [%0], [%1], 16;"
                 :: "r"(smem_dst), "l"(gsrc));
}
#define CP_COMMIT() asm volatile("cp.async.commit_group;" ::: "memory")
#define CP_WAIT(N)  asm volatile("cp.async.wait_group %0;" :: "n"(N) : "memory")

// smem tile layout: pitch 136 bf16 (272B = 17*16B -> conflict-free ldmatrix)
#define PITCH 136
#define TILE_BYTES (128 * PITCH * 2)             // 34816
#define OFF_AH 0
#define OFF_AL (OFF_AH + TILE_BYTES)
#define OFF_B0H (OFF_AL + TILE_BYTES)
#define OFF_B0L (OFF_B0H + TILE_BYTES)
#define OFF_B1H (OFF_B0L + TILE_BYTES)
#define OFF_B1L (OFF_B1H + TILE_BYTES)
#define GEMM_SMEM (OFF_B1L + TILE_BYTES)         // 208896, 1 CTA/SM

// ---------------------------------------------------------------------------
// Transpose + split W: Wt[mat][n][k] = W_mat[k][n]
// ---------------------------------------------------------------------------
__global__ __launch_bounds__(256)
void prep_w_kernel(const float* __restrict__ Wq, const float* __restrict__ Wk,
                   const float* __restrict__ Wv) {
    int gid = blockIdx.x * blockDim.x + threadIdx.x;
    if (gid >= 3 * HID * HID) return;
    int mat = gid >> 14;
    int nn  = (gid >> 7) & 127;
    int k   = gid & 127;
    const float* W = (mat == 0) ? Wq : (mat == 1) ? Wk : Wv;
    float x = W[k * HID + nn];
    __nv_bfloat16 hi = __float2bfloat16_rn(x);
    __nv_bfloat16 lo = __float2bfloat16_rn(x - __bfloat162float(hi));
    g_wt_hi[gid] = hi;
    g_wt_lo[gid] = lo;
}

// ---------------------------------------------------------------------------
// GEMM pieces
// ---------------------------------------------------------------------------
__device__ __forceinline__ void load_B_async(int tid, uint32_t sb, int mat,
                                             uint32_t offH, uint32_t offL) {
    const uint4* srcH = reinterpret_cast<const uint4*>(g_wt_hi + (size_t)mat * HID * HID);
    const uint4* srcL = reinterpret_cast<const uint4*>(g_wt_lo + (size_t)mat * HID * HID);
#pragma unroll
    for (int it = 0; it < 8; it++) {
        int t = tid + it * 256;
        int r = t >> 4;
        int c = t & 15;
        uint32_t doff = (uint32_t)(r * (PITCH * 2) + c * 16);
        cp16(sb + offH + doff, srcH + t);
        cp16(sb + offL + doff, srcL + t);
    }
}

// Compute one mat: 8 warps, wm = wid&3 (32 rows), wn = wid>>2 (64 cols).
__device__ __forceinline__ void compute_mat(
    uint32_t sb, uint32_t offBH, uint32_t offBL,
    int row0, int wm, int wn, int lane,
    float* __restrict__ out, const float* __restrict__ bias) {

    const int a_lrow = lane & 15;
    const int a_lsel = lane >> 4;
    const int b_lrow = (lane & 7) + ((lane >> 4) & 1) * 8;
    const int b_lk   = ((lane >> 3) & 1) * 8;

    float acc[2][8][4];
#pragma unroll
    for (int mi = 0; mi < 2; mi++)
#pragma unroll
        for (int ni = 0; ni < 8; ni++)
#pragma unroll
            for (int r = 0; r < 4; r++) acc[mi][ni][r] = 0.f;

#pragma unroll
    for (int ks = 0; ks < 8; ks++) {
        uint32_t aH[2][4], aL[2][4], bH[4][4], bL[4][4];
#pragma unroll
        for (int mi = 0; mi < 2; mi++) {
            uint32_t off = (uint32_t)(((wm * 32 + mi * 16 + a_lrow) * PITCH +
                                       ks * 16 + a_lsel * 8) * 2);
            ldsm_x4(aH[mi], sb + OFF_AH + off);
            ldsm_x4(aL[mi], sb + OFF_AL + off);
        }
#pragma unroll
        for (int np = 0; np < 4; np++) {
            uint32_t off = (uint32_t)(((wn * 64 + np * 16 + b_lrow) * PITCH +
                                       ks * 16 + b_lk) * 2);
            ldsm_x4(bH[np], sb + offBH + off);
            ldsm_x4(bL[np], sb + offBL + off);
        }
#pragma unroll
        for (int mi = 0; mi < 2; mi++)
#pragma unroll
            for (int ni = 0; ni < 8; ni++) {
                int np = ni >> 1, rb = (ni & 1) * 2;
                mma_bf16(acc[mi][ni], aH[mi], bH[np][rb], bH[np][rb + 1]);
                mma_bf16(acc[mi][ni], aH[mi], bL[np][rb], bL[np][rb + 1]);
                mma_bf16(acc[mi][ni], aL[mi], bH[np][rb], bH[np][rb + 1]);
            }
    }

#pragma unroll
    for (int mi = 0; mi < 2; mi++) {
        int row = row0 + wm * 32 + mi * 16 + (lane >> 2);
#pragma unroll
        for (int ni = 0; ni < 8; ni++) {
            int col = wn * 64 + ni * 8 + (lane & 3) * 2;
            float bx = __ldg(&bias[col]);
            float by = __ldg(&bias[col + 1]);
            *reinterpret_cast<float2*>(&out[(size_t)row * HID + col]) =
                make_float2(acc[mi][ni][0] + bx, acc[mi][ni][1] + by);
            *reinterpret_cast<float2*>(&out[(size_t)(row + 8) * HID + col]) =
                make_float2(acc[mi][ni][2] + bx, acc[mi][ni][3] + by);
        }
    }
}

// ---------------------------------------------------------------------------
// Pipelined GEMM: block = 128 rows x 128 cols, K=128 resident.
// ---------------------------------------------------------------------------
__global__ __launch_bounds__(256)
void qkv_gemm_pipe(const float* __restrict__ h,
                   const float* __restrict__ bq, const float* __restrict__ bk,
                   const float* __restrict__ bv, int n) {
    extern __shared__ __align__(16) char smem[];
    const uint32_t sb = smem_u32(smem);
    const int tid  = threadIdx.x;
    const int wid  = tid >> 5;
    const int lane = tid & 31;
    const int wm   = wid & 3;
    const int wn   = wid >> 2;
    const int row0 = blockIdx.x * 128;

    load_B_async(tid, sb, 0, OFF_B0H, OFF_B0L);
    CP_COMMIT();

    // Stage A: load fp32 h rows, split to bf16 hi/lo, store pitch-136.
    for (int t = tid; t < 4096; t += 256) {
        int r = t >> 5;
        int c = t & 31;
        int row = row0 + r;
        float4 v = make_float4(0.f, 0.f, 0.f, 0.f);
        if (row < n)
            v = *reinterpret_cast<const float4*>(h + (size_t)row * HID + c * 4);
        float hx = __bfloat162float(__float2bfloat16_rn(v.x));
        float hy = __bfloat162float(__float2bfloat16_rn(v.y));
        float hz = __bfloat162float(__float2bfloat16_rn(v.z));
        float hw = __bfloat162float(__float2bfloat16_rn(v.w));
        uint2 phi, plo;
        phi.x = bf2_bits(v.x, v.y);
        phi.y = bf2_bits(v.z, v.w);
        plo.x = bf2_bits(v.x - hx, v.y - hy);
        plo.y = bf2_bits(v.z - hz, v.w - hw);
        uint32_t doff = (uint32_t)(r * (PITCH * 2) + c * 8);
        *reinterpret_cast<uint2*>(smem + OFF_AH + doff) = phi;
        *reinterpret_cast<uint2*>(smem + OFF_AL + doff) = plo;
    }

    // ---- mat 0 ----
    load_B_async(tid, sb, 1, OFF_B1H, OFF_B1L);
    CP_COMMIT();
    CP_WAIT(1);
    __syncthreads();
    compute_mat(sb, OFF_B0H, OFF_B0L, row0, wm, wn, lane, g_Q, bq);
    __syncthreads();

    // ---- mat 1 ----
    load_B_async(tid, sb, 2, OFF_B0H, OFF_B0L);
    CP_COMMIT();
    CP_WAIT(1);
    __syncthreads();
    compute_mat(sb, OFF_B1H, OFF_B1L, row0, wm, wn, lane, g_K, bk);
    __syncthreads();

    // ---- mat 2 ----
    CP_WAIT(0);
    __syncthreads();
    compute_mat(sb, OFF_B0H, OFF_B0L, row0, wm, wn, lane, g_V, bv);
}

// ---------------------------------------------------------------------------
// CSR construction by destination
// ---------------------------------------------------------------------------
__global__ void zero_kernel(int n) {
    int gid = blockIdx.x * blockDim.x + threadIdx.x;
    if (gid < n) { g_cnt[gid] = 0; g_cursor[gid] = 0; }
}

__global__ void hist_kernel(const int* __restrict__ dst, int e) {
    int gid = blockIdx.x * blockDim.x + threadIdx.x;
    if (gid < e) atomicAdd(&g_cnt[dst[gid]], 1);
}

__global__ void scan_block_kernel(int n) {
    __shared__ int sm[1024];
    int tid = threadIdx.x;
    int gid = blockIdx.x * 1024 + tid;
    int v = (gid < n) ? g_cnt[gid] : 0;
    sm[tid] = v;
    __syncthreads();
    for (int off = 1; off < 1024; off <<= 1) {
        int t = (tid >= off) ? sm[tid - off] : 0;
        __syncthreads();
        sm[tid] += t;
        __syncthreads();
    }
    if (gid < n) g_rowptr[gid] = sm[tid] - v;  // exclusive within block
    if (tid == 1023) g_blksum[blockIdx.x] = sm[1023];
}

// Parallel top-level scan over <=128 block sums (Hillis-Steele in smem).
__global__ void scan_top_kernel(int nb) {
    __shared__ int sm[128];
    int tid = threadIdx.x;
    int v = (tid < nb) ? g_blksum[tid] : 0;
    sm[tid] = v;
    __syncthreads();
    for (int off = 1; off < 128; off <<= 1) {
        int t = (tid >= off) ? sm[tid - off] : 0;
        __syncthreads();
        sm[tid] += t;
        __syncthreads();
    }
    if (tid < nb) g_blksum[tid] = sm[tid] - v;  // exclusive
}

__global__ void add_off_kernel(int n, int e) {
    int gid = blockIdx.x * blockDim.x + threadIdx.x;
    if (gid < n) g_rowptr[gid] += g_blksum[gid >> 10];
    if (gid == 0) g_rowptr[n] = e;
}

__global__ void scatter_kernel(const int* __restrict__ src,
                               const int* __restrict__ dst, int e) {
    int gid = blockIdx.x * blockDim.x + threadIdx.x;
    if (gid < e) {
        int d = dst[gid];
        int pos = g_rowptr[d] + atomicAdd(&g_cursor[d], 1);
        g_ssrc[pos] = src[gid];
    }
}

// ---------------------------------------------------------------------------
// One warp per destination node, online softmax; edge loop software-pipelined
// (prefetch next index + K/V rows, MLP ~3).
// ---------------------------------------------------------------------------
__global__ __launch_bounds__(256)
void attn_kernel(float* __restrict__ out, int n) {
    int gwarp = (blockIdx.x * blockDim.x + threadIdx.x) >> 5;
    if (gwarp >= n) return;
    int lane = threadIdx.x & 31;

    const float4* Q4 = reinterpret_cast<const float4*>(g_Q);
    const float4* K4 = reinterpret_cast<const float4*>(g_K);
    const float4* V4 = reinterpret_cast<const float4*>(g_V);

    float4 q = Q4[(size_t)gwarp * 32 + lane];
    int beg = g_rowptr[gwarp];
    int end = g_rowptr[gwarp + 1];

    if (end <= beg) {
        reinterpret_cast<float4*>(out)[(size_t)gwarp * 32 + lane] =
            make_float4(0.f, 0.f, 0.f, 0.f);
        return;
    }

    float m = -__int_as_float(0x7f800000);  // -inf
    float s = 0.0f;
    float4 acc = make_float4(0.f, 0.f, 0.f, 0.f);

    // prologue: load edge 0
    int sidx = __ldg(&g_ssrc[beg]);
    float4 k = K4[(size_t)sidx * 32 + lane];
    float4 v = V4[(size_t)sidx * 32 + lane];

    for (int idx = beg; idx < end; idx++) {
        // prefetch next edge (clamped -> always safe, no divergence)
        int pidx = idx + 1 < end ? idx + 1 : idx;
        int nsidx = __ldg(&g_ssrc[pidx]);
        float4 nk = K4[(size_t)nsidx * 32 + lane];
        float4 nv = V4[(size_t)nsidx * 32 + lane];

        float sc = k.x * q.x + k.y * q.y + k.z * q.z + k.w * q.w;
        sc += __shfl_xor_sync(0xffffffffu, sc, 1);
        sc += __shfl_xor_sync(0xffffffffu, sc, 2);
        float mn = fmaxf(m, sc);
        float scale = __expf(m - mn);   // first iter: exp(-inf) = 0
        float p = __expf(sc - mn);
        s = s * scale + p;
        acc.x = acc.x * scale + p * v.x;
        acc.y = acc.y * scale + p * v.y;
        acc.z = acc.z * scale + p * v.z;
        acc.w = acc.w * scale + p * v.w;
        m = mn;

        k = nk; v = nv;
    }

    float inv = 1.0f / s;
    reinterpret_cast<float4*>(out)[(size_t)gwarp * 32 + lane] =
        make_float4(acc.x * inv, acc.y * inv, acc.z * inv, acc.w * inv);
}

// ---------------------------------------------------------------------------
extern "C" void kernel_launch(void* const* d_in, const int* in_sizes, int n_in,
                              void* d_out, int out_size) {
    const float* h   = (const float*)d_in[0];
    const int*   src = (const int*)d_in[1];
    const int*   dst = (const int*)d_in[2];
    const float* Wq  = (const float*)d_in[3];
    const float* bq  = (const float*)d_in[4];
    const float* Wk  = (const float*)d_in[5];
    const float* bk  = (const float*)d_in[6];
    const float* Wv  = (const float*)d_in[7];
    const float* bv  = (const float*)d_in[8];
    float* out = (float*)d_out;

    int n = in_sizes[0] / HID;
    int e = in_sizes[1];

    // One-time infra (created on the uncaptured correctness call).
    static cudaStream_t s2 = nullptr;
    static cudaEvent_t ev_fork = nullptr, ev_join = nullptr;
    if (s2 == nullptr) {
        cudaStreamCreateWithFlags(&s2, cudaStreamNonBlocking);
        cudaEventCreateWithFlags(&ev_fork, cudaEventDisableTiming);
        cudaEventCreateWithFlags(&ev_join, cudaEventDisableTiming);
        cudaFuncSetAttribute(qkv_gemm_pipe,
                             cudaFuncAttributeMaxDynamicSharedMemorySize,
                             GEMM_SMEM);
    }

    // Fork: CSR chain on s2, GEMM chain on the main (capture) stream.
    // Launch-call order puts qkv_gemm_pipe 4th (the launch ncu captures).
    cudaEventRecord(ev_fork, 0);
    cudaStreamWaitEvent(s2, ev_fork, 0);

    zero_kernel<<<(n + 255) / 256, 256, 0, s2>>>(n);          // launch 1
    hist_kernel<<<(e + 255) / 256, 256, 0, s2>>>(dst, e);     // launch 2
    prep_w_kernel<<<(3 * HID * HID + 255) / 256, 256>>>(Wq, Wk, Wv);  // 3
    int mblocks = (n + 127) / 128;
    qkv_gemm_pipe<<<mblocks, 256, GEMM_SMEM>>>(h, bq, bk, bv, n);     // 4

    int nb = (n + 1023) / 1024;
    scan_block_kernel<<<nb, 1024, 0, s2>>>(n);                // 5
    scan_top_kernel<<<1, 128, 0, s2>>>(nb);                   // 6
    add_off_kernel<<<(n + 255) / 256, 256, 0, s2>>>(n, e);    // 7
    scatter_kernel<<<(e + 255) / 256, 256, 0, s2>>>(src, dst, e);  // 8
    cudaEventRecord(ev_join, s2);

    // Join, then attention.
    cudaStreamWaitEvent(0, ev_join, 0);
    long long total_threads = (long long)n * 32;
    int attn_blocks = (int)((total_threads + 255) / 256);
    attn_kernel<<<attn_blocks, 256>>>(out, n);                // 9
}

// round 9
// speedup vs baseline: 1.1031x; 1.1031x over previous
#include <cuda_runtime.h>
#include <cuda_bf16.h>
#include <cstdint>

// ---------------------------------------------------------------------------
// Graph attention: QKV projections (mma.sync bf16 split GEMM, 512 threads /
// 16 warps per CTA for 4 warps/SMSP) + dst-sorted CSR (forked stream) +
// warp-per-node online softmax.
// ---------------------------------------------------------------------------

#define HID 128
#define MAXN 100352           // 784 * 128, >= N
#define MAXE 1700000

__device__ float g_Q[(size_t)MAXN * HID];
__device__ float g_K[(size_t)MAXN * HID];
__device__ float g_V[(size_t)MAXN * HID];
__device__ __nv_bfloat16 g_wt_hi[3 * HID * HID];  // [mat][n][k] = W[k][n]
__device__ __nv_bfloat16 g_wt_lo[3 * HID * HID];
__device__ int   g_cnt[MAXN];
__device__ int   g_cursor[MAXN];
__device__ int   g_rowptr[MAXN + 1];
__device__ int   g_blksum[256];
__device__ int   g_ssrc[MAXE];

// ---------------------------------------------------------------------------
__device__ __forceinline__ uint32_t smem_u32(const void* p) {
    uint32_t a;
    asm("{ .reg .u64 t; cvta.to.shared.u64 t, %1; cvt.u32.u64 %0, t; }"
        : "=r"(a) : "l"(p));
    return a;
}
__device__ __forceinline__ void ldsm_x4(uint32_t* d, uint32_t addr) {
    asm volatile("ldmatrix.sync.aligned.m8n8.x4.shared.b16 {%0,%1,%2,%3}, [%4];"
                 : "=r"(d[0]), "=r"(d[1]), "=r"(d[2]), "=r"(d[3]) : "r"(addr));
}
__device__ __forceinline__ void mma_bf16(float* c, const uint32_t* a,
                                         uint32_t b0, uint32_t b1) {
    asm volatile("mma.sync.aligned.m16n8k16.row.col.f32.bf16.bf16.f32 "
                 "{%0,%1,%2,%3}, {%4,%5,%6,%7}, {%8,%9}, {%0,%1,%2,%3};"
                 : "+f"(c[0]), "+f"(c[1]), "+f"(c[2]), "+f"(c[3])
                 : "r"(a[0]), "r"(a[1]), "r"(a[2]), "r"(a[3]),
                   "r"(b0), "r"(b1));
}
__device__ __forceinline__ uint32_t bf2_bits(float x, float y) {
    __nv_bfloat162 t(__float2bfloat16_rn(x), __float2bfloat16_rn(y));
    return *reinterpret_cast<uint32_t*>(&t);
}
__device__ __forceinline__ void cp16(uint32_t smem_dst, const void* gsrc) {
    asm volatile("cp.async.cg.shared.global [%0], [%1], 16;"
                 :: "r"(smem_dst), "l"(gsrc));
}
#define CP_COMMIT() asm volatile("cp.async.commit_group;" ::: "memory")
#define CP_WAIT(N)  asm volatile("cp.async.wait_group %0;" :: "n"(N) : "memory")

// smem tile layout: pitch 136 bf16 (272B = 17*16B -> conflict-free ldmatrix)
#define PITCH 136
#define TILE_BYTES (128 * PITCH * 2)             // 34816
#define OFF_AH 0
#define OFF_AL (OFF_AH + TILE_BYTES)
#define OFF_BH (OFF_AL + TILE_BYTES)
#define OFF_BL (OFF_BH + TILE_BYTES)
#define GEMM_SMEM (OFF_BL + TILE_BYTES)          // 139264

#define GEMM_THREADS 512

// ---------------------------------------------------------------------------
// Transpose + split W: Wt[mat][n][k] = W_mat[k][n]
// ---------------------------------------------------------------------------
__global__ __launch_bounds__(256)
void prep_w_kernel(const float* __restrict__ Wq, const float* __restrict__ Wk,
                   const float* __restrict__ Wv) {
    int gid = blockIdx.x * blockDim.x + threadIdx.x;
    if (gid >= 3 * HID * HID) return;
    int mat = gid >> 14;
    int nn  = (gid >> 7) & 127;
    int k   = gid & 127;
    const float* W = (mat == 0) ? Wq : (mat == 1) ? Wk : Wv;
    float x = W[k * HID + nn];
    __nv_bfloat16 hi = __float2bfloat16_rn(x);
    __nv_bfloat16 lo = __float2bfloat16_rn(x - __bfloat162float(hi));
    g_wt_hi[gid] = hi;
    g_wt_lo[gid] = lo;
}

// ---------------------------------------------------------------------------
__device__ __forceinline__ void load_B_async(int tid, uint32_t sb, int mat) {
    const uint4* srcH = reinterpret_cast<const uint4*>(g_wt_hi + (size_t)mat * HID * HID);
    const uint4* srcL = reinterpret_cast<const uint4*>(g_wt_lo + (size_t)mat * HID * HID);
#pragma unroll
    for (int it = 0; it < 4; it++) {
        int t = tid + it * GEMM_THREADS;
        int r = t >> 4;
        int c = t & 15;
        uint32_t doff = (uint32_t)(r * (PITCH * 2) + c * 16);
        cp16(sb + OFF_BH + doff, srcH + t);
        cp16(sb + OFF_BL + doff, srcL + t);
    }
}

// Compute one mat: 16 warps, wm = wid&3 (32 rows), wn = wid>>2 (32 cols).
__device__ __forceinline__ void compute_mat(
    uint32_t sb, int row0, int wm, int wn, int lane,
    float* __restrict__ out, const float* __restrict__ bias) {

    const int a_lrow = lane & 15;
    const int a_lsel = lane >> 4;
    const int b_lrow = (lane & 7) + ((lane >> 4) & 1) * 8;
    const int b_lk   = ((lane >> 3) & 1) * 8;

    float acc[2][4][4];
#pragma unroll
    for (int mi = 0; mi < 2; mi++)
#pragma unroll
        for (int ni = 0; ni < 4; ni++)
#pragma unroll
            for (int r = 0; r < 4; r++) acc[mi][ni][r] = 0.f;

#pragma unroll
    for (int ks = 0; ks < 8; ks++) {
        uint32_t aH[2][4], aL[2][4], bH[2][4], bL[2][4];
#pragma unroll
        for (int mi = 0; mi < 2; mi++) {
            uint32_t off = (uint32_t)(((wm * 32 + mi * 16 + a_lrow) * PITCH +
                                       ks * 16 + a_lsel * 8) * 2);
            ldsm_x4(aH[mi], sb + OFF_AH + off);
            ldsm_x4(aL[mi], sb + OFF_AL + off);
        }
#pragma unroll
        for (int np = 0; np < 2; np++) {
            uint32_t off = (uint32_t)(((wn * 32 + np * 16 + b_lrow) * PITCH +
                                       ks * 16 + b_lk) * 2);
            ldsm_x4(bH[np], sb + OFF_BH + off);
            ldsm_x4(bL[np], sb + OFF_BL + off);
        }
#pragma unroll
        for (int mi = 0; mi < 2; mi++)
#pragma unroll
            for (int ni = 0; ni < 4; ni++) {
                int np = ni >> 1, rb = (ni & 1) * 2;
                mma_bf16(acc[mi][ni], aH[mi], bH[np][rb], bH[np][rb + 1]);
                mma_bf16(acc[mi][ni], aH[mi], bL[np][rb], bL[np][rb + 1]);
                mma_bf16(acc[mi][ni], aL[mi], bH[np][rb], bH[np][rb + 1]);
            }
    }

#pragma unroll
    for (int mi = 0; mi < 2; mi++) {
        int row = row0 + wm * 32 + mi * 16 + (lane >> 2);
#pragma unroll
        for (int ni = 0; ni < 4; ni++) {
            int col = wn * 32 + ni * 8 + (lane & 3) * 2;
            float bx = __ldg(&bias[col]);
            float by = __ldg(&bias[col + 1]);
            *reinterpret_cast<float2*>(&out[(size_t)row * HID + col]) =
                make_float2(acc[mi][ni][0] + bx, acc[mi][ni][1] + by);
            *reinterpret_cast<float2*>(&out[(size_t)(row + 8) * HID + col]) =
                make_float2(acc[mi][ni][2] + bx, acc[mi][ni][3] + by);
        }
    }
}

// ---------------------------------------------------------------------------
// GEMM: block = 128 rows x 128 cols, K=128 resident, 512 threads (16 warps).
// ---------------------------------------------------------------------------
__global__ __launch_bounds__(GEMM_THREADS)
void qkv_gemm_wide(const float* __restrict__ h,
                   const float* __restrict__ bq, const float* __restrict__ bk,
                   const float* __restrict__ bv, int n) {
    extern __shared__ __align__(16) char smem[];
    const uint32_t sb = smem_u32(smem);
    const int tid  = threadIdx.x;
    const int wid  = tid >> 5;
    const int lane = tid & 31;
    const int wm   = wid & 3;
    const int wn   = wid >> 2;
    const int row0 = blockIdx.x * 128;

    load_B_async(tid, sb, 0);
    CP_COMMIT();

    // Stage A: load fp32 h rows, split to bf16 hi/lo, store pitch-136.
    for (int t = tid; t < 4096; t += GEMM_THREADS) {
        int r = t >> 5;
        int c = t & 31;
        int row = row0 + r;
        float4 v = make_float4(0.f, 0.f, 0.f, 0.f);
        if (row < n)
            v = *reinterpret_cast<const float4*>(h + (size_t)row * HID + c * 4);
        float hx = __bfloat162float(__float2bfloat16_rn(v.x));
        float hy = __bfloat162float(__float2bfloat16_rn(v.y));
        float hz = __bfloat162float(__float2bfloat16_rn(v.z));
        float hw = __bfloat162float(__float2bfloat16_rn(v.w));
        uint2 phi, plo;
        phi.x = bf2_bits(v.x, v.y);
        phi.y = bf2_bits(v.z, v.w);
        plo.x = bf2_bits(v.x - hx, v.y - hy);
        plo.y = bf2_bits(v.z - hz, v.w - hw);
        uint32_t doff = (uint32_t)(r * (PITCH * 2) + c * 8);
        *reinterpret_cast<uint2*>(smem + OFF_AH + doff) = phi;
        *reinterpret_cast<uint2*>(smem + OFF_AL + doff) = plo;
    }

    // ---- mat 0 (Q) ----
    CP_WAIT(0);
    __syncthreads();
    compute_mat(sb, row0, wm, wn, lane, g_Q, bq);
    __syncthreads();

    // ---- mat 1 (K) ----
    load_B_async(tid, sb, 1);
    CP_COMMIT();
    CP_WAIT(0);
    __syncthreads();
    compute_mat(sb, row0, wm, wn, lane, g_K, bk);
    __syncthreads();

    // ---- mat 2 (V) ----
    load_B_async(tid, sb, 2);
    CP_COMMIT();
    CP_WAIT(0);
    __syncthreads();
    compute_mat(sb, row0, wm, wn, lane, g_V, bv);
}

// ---------------------------------------------------------------------------
// CSR construction by destination
// ---------------------------------------------------------------------------
__global__ void zero_kernel(int n) {
    int gid = blockIdx.x * blockDim.x + threadIdx.x;
    if (gid < n) { g_cnt[gid] = 0; g_cursor[gid] = 0; }
}

__global__ void hist_kernel(const int* __restrict__ dst, int e) {
    int gid = blockIdx.x * blockDim.x + threadIdx.x;
    if (gid < e) atomicAdd(&g_cnt[dst[gid]], 1);
}

__global__ void scan_block_kernel(int n) {
    __shared__ int sm[1024];
    int tid = threadIdx.x;
    int gid = blockIdx.x * 1024 + tid;
    int v = (gid < n) ? g_cnt[gid] : 0;
    sm[tid] = v;
    __syncthreads();
    for (int off = 1; off < 1024; off <<= 1) {
        int t = (tid >= off) ? sm[tid - off] : 0;
        __syncthreads();
        sm[tid] += t;
        __syncthreads();
    }
    if (gid < n) g_rowptr[gid] = sm[tid] - v;  // exclusive within block
    if (tid == 1023) g_blksum[blockIdx.x] = sm[1023];
}

// Parallel top-level scan over <=128 block sums (Hillis-Steele in smem).
__global__ void scan_top_kernel(int nb) {
    __shared__ int sm[128];
    int tid = threadIdx.x;
    int v = (tid < nb) ? g_blksum[tid] : 0;
    sm[tid] = v;
    __syncthreads();
    for (int off = 1; off < 128; off <<= 1) {
        int t = (tid >= off) ? sm[tid - off] : 0;
        __syncthreads();
        sm[tid] += t;
        __syncthreads();
    }
    if (tid < nb) g_blksum[tid] = sm[tid] - v;  // exclusive
}

__global__ void add_off_kernel(int n, int e) {
    int gid = blockIdx.x * blockDim.x + threadIdx.x;
    if (gid < n) g_rowptr[gid] += g_blksum[gid >> 10];
    if (gid == 0) g_rowptr[n] = e;
}

__global__ void scatter_kernel(const int* __restrict__ src,
                               const int* __restrict__ dst, int e) {
    int gid = blockIdx.x * blockDim.x + threadIdx.x;
    if (gid < e) {
        int d = dst[gid];
        int pos = g_rowptr[d] + atomicAdd(&g_cursor[d], 1);
        g_ssrc[pos] = src[gid];
    }
}

// ---------------------------------------------------------------------------
// One warp per destination node, online softmax in registers.
// ---------------------------------------------------------------------------
__global__ __launch_bounds__(256)
void attn_kernel(float* __restrict__ out, int n) {
    int gwarp = (blockIdx.x * blockDim.x + threadIdx.x) >> 5;
    if (gwarp >= n) return;
    int lane = threadIdx.x & 31;

    const float4* Q4 = reinterpret_cast<const float4*>(g_Q);
    const float4* K4 = reinterpret_cast<const float4*>(g_K);
    const float4* V4 = reinterpret_cast<const float4*>(g_V);

    float4 q = Q4[(size_t)gwarp * 32 + lane];
    int beg = g_rowptr[gwarp];
    int end = g_rowptr[gwarp + 1];

    float m = -__int_as_float(0x7f800000);  // -inf
    float s = 0.0f;
    float4 acc = make_float4(0.f, 0.f, 0.f, 0.f);

    for (int idx = beg; idx < end; idx++) {
        int sidx = __ldg(&g_ssrc[idx]);
        float4 k = K4[(size_t)sidx * 32 + lane];
        float sc = k.x * q.x + k.y * q.y + k.z * q.z + k.w * q.w;
        sc += __shfl_xor_sync(0xffffffffu, sc, 1);
        sc += __shfl_xor_sync(0xffffffffu, sc, 2);
        float mn = fmaxf(m, sc);
        float scale = __expf(m - mn);   // first iter: exp(-inf) = 0
        float p = __expf(sc - mn);
        float4 v = V4[(size_t)sidx * 32 + lane];
        s = s * scale + p;
        acc.x = acc.x * scale + p * v.x;
        acc.y = acc.y * scale + p * v.y;
        acc.z = acc.z * scale + p * v.z;
        acc.w = acc.w * scale + p * v.w;
        m = mn;
    }

    float4 o;
    if (end > beg) {
        float inv = 1.0f / s;
        o = make_float4(acc.x * inv, acc.y * inv, acc.z * inv, acc.w * inv);
    } else {
        o = make_float4(0.f, 0.f, 0.f, 0.f);
    }
    reinterpret_cast<float4*>(out)[(size_t)gwarp * 32 + lane] = o;
}

// ---------------------------------------------------------------------------
extern "C" void kernel_launch(void* const* d_in, const int* in_sizes, int n_in,
                              void* d_out, int out_size) {
    const float* h   = (const float*)d_in[0];
    const int*   src = (const int*)d_in[1];
    const int*   dst = (const int*)d_in[2];
    const float* Wq  = (const float*)d_in[3];
    const float* bq  = (const float*)d_in[4];
    const float* Wk  = (const float*)d_in[5];
    const float* bk  = (const float*)d_in[6];
    const float* Wv  = (const float*)d_in[7];
    const float* bv  = (const float*)d_in[8];
    float* out = (float*)d_out;

    int n = in_sizes[0] / HID;
    int e = in_sizes[1];

    // One-time infra (created on the uncaptured correctness call).
    static cudaStream_t s2 = nullptr;
    static cudaEvent_t ev_fork = nullptr, ev_join = nullptr;
    if (s2 == nullptr) {
        cudaStreamCreateWithFlags(&s2, cudaStreamNonBlocking);
        cudaEventCreateWithFlags(&ev_fork, cudaEventDisableTiming);
        cudaEventCreateWithFlags(&ev_join, cudaEventDisableTiming);
        cudaFuncSetAttribute(qkv_gemm_wide,
                             cudaFuncAttributeMaxDynamicSharedMemorySize,
                             GEMM_SMEM);
    }

    // Fork: CSR chain on s2, GEMM chain on the main (capture) stream.
    // Launch-call order puts qkv_gemm_wide 4th (the launch ncu captures).
    cudaEventRecord(ev_fork, 0);
    cudaStreamWaitEvent(s2, ev_fork, 0);

    zero_kernel<<<(n + 255) / 256, 256, 0, s2>>>(n);          // launch 1
    hist_kernel<<<(e + 255) / 256, 256, 0, s2>>>(dst, e);     // launch 2
    prep_w_kernel<<<(3 * HID * HID + 255) / 256, 256>>>(Wq, Wk, Wv);  // 3
    int mblocks = (n + 127) / 128;
    qkv_gemm_wide<<<mblocks, GEMM_THREADS, GEMM_SMEM>>>(h, bq, bk, bv, n); // 4

    int nb = (n + 1023) / 1024;
    scan_block_kernel<<<nb, 1024, 0, s2>>>(n);                // 5
    scan_top_kernel<<<1, 128, 0, s2>>>(nb);                   // 6
    add_off_kernel<<<(n + 255) / 256, 256, 0, s2>>>(n, e);    // 7
    scatter_kernel<<<(e + 255) / 256, 256, 0, s2>>>(src, dst, e);  // 8
    cudaEventRecord(ev_join, s2);

    // Join, then attention.
    cudaStreamWaitEvent(0, ev_join, 0);
    long long total_threads = (long long)n * 32;
    int attn_blocks = (int)((total_threads + 255) / 256);
    attn_kernel<<<attn_blocks, 256>>>(out, n);                // 9
}

// round 10
// speedup vs baseline: 1.1377x; 1.0313x over previous
#include <cuda_runtime.h>
#include <cuda_bf16.h>
#include <cstdint>

// ---------------------------------------------------------------------------
// Graph attention: QKV projections (mma.sync bf16 split GEMM, 512 threads,
// register-pipelined k-steps + double-buffered B) + dst-sorted CSR (forked
// stream) + warp-per-node online softmax.
// ---------------------------------------------------------------------------

#define HID 128
#define MAXN 100352           // 784 * 128, >= N
#define MAXE 1700000

__device__ float g_Q[(size_t)MAXN * HID];
__device__ float g_K[(size_t)MAXN * HID];
__device__ float g_V[(size_t)MAXN * HID];
__device__ __nv_bfloat16 g_wt_hi[3 * HID * HID];  // [mat][n][k] = W[k][n]
__device__ __nv_bfloat16 g_wt_lo[3 * HID * HID];
__device__ int   g_cnt[MAXN];
__device__ int   g_cursor[MAXN];
__device__ int   g_rowptr[MAXN + 1];
__device__ int   g_blksum[256];
__device__ int   g_ssrc[MAXE];

// ---------------------------------------------------------------------------
__device__ __forceinline__ uint32_t smem_u32(const void* p) {
    uint32_t a;
    asm("{ .reg .u64 t; cvta.to.shared.u64 t, %1; cvt.u32.u64 %0, t; }"
        : "=r"(a) : "l"(p));
    return a;
}
__device__ __forceinline__ void ldsm_x4(uint32_t* d, uint32_t addr) {
    asm volatile("ldmatrix.sync.aligned.m8n8.x4.shared.b16 {%0,%1,%2,%3}, [%4];"
                 : "=r"(d[0]), "=r"(d[1]), "=r"(d[2]), "=r"(d[3]) : "r"(addr));
}
__device__ __forceinline__ void mma_bf16(float* c, const uint32_t* a,
                                         uint32_t b0, uint32_t b1) {
    asm volatile("mma.sync.aligned.m16n8k16.row.col.f32.bf16.bf16.f32 "
                 "{%0,%1,%2,%3}, {%4,%5,%6,%7}, {%8,%9}, {%0,%1,%2,%3};"
                 : "+f"(c[0]), "+f"(c[1]), "+f"(c[2]), "+f"(c[3])
                 : "r"(a[0]), "r"(a[1]), "r"(a[2]), "r"(a[3]),
                   "r"(b0), "r"(b1));
}
__device__ __forceinline__ uint32_t bf2_bits(float x, float y) {
    __nv_bfloat162 t(__float2bfloat16_rn(x), __float2bfloat16_rn(y));
    return *reinterpret_cast<uint32_t*>(&t);
}
__device__ __forceinline__ void cp16(uint32_t smem_dst, const void* gsrc) {
    asm volatile("cp.async.cg.shared.global [%0], [%1], 16;"
                 :: "r"(smem_dst), "l"(gsrc));
}
#define CP_COMMIT() asm volatile("cp.async.commit_group;" ::: "memory")
#define CP_WAIT(N)  asm volatile("cp.async.wait_group %0;" :: "n"(N) : "memory")

// smem tile layout: pitch 136 bf16 (272B = 17*16B -> conflict-free ldmatrix)
#define PITCH 136
#define TILE_BYTES (128 * PITCH * 2)             // 34816
#define OFF_AH 0
#define OFF_AL (OFF_AH + TILE_BYTES)
#define OFF_B0H (OFF_AL + TILE_BYTES)
#define OFF_B0L (OFF_B0H + TILE_BYTES)
#define OFF_B1H (OFF_B0L + TILE_BYTES)
#define OFF_B1L (OFF_B1H + TILE_BYTES)
#define GEMM_SMEM (OFF_B1L + TILE_BYTES)         // 208896

#define GEMM_THREADS 512

// ---------------------------------------------------------------------------
// Transpose + split W: Wt[mat][n][k] = W_mat[k][n]
// ---------------------------------------------------------------------------
__global__ __launch_bounds__(256)
void prep_w_kernel(const float* __restrict__ Wq, const float* __restrict__ Wk,
                   const float* __restrict__ Wv) {
    int gid = blockIdx.x * blockDim.x + threadIdx.x;
    if (gid >= 3 * HID * HID) return;
    int mat = gid >> 14;
    int nn  = (gid >> 7) & 127;
    int k   = gid & 127;
    const float* W = (mat == 0) ? Wq : (mat == 1) ? Wk : Wv;
    float x = W[k * HID + nn];
    __nv_bfloat16 hi = __float2bfloat16_rn(x);
    __nv_bfloat16 lo = __float2bfloat16_rn(x - __bfloat162float(hi));
    g_wt_hi[gid] = hi;
    g_wt_lo[gid] = lo;
}

// ---------------------------------------------------------------------------
__device__ __forceinline__ void load_B_async(int tid, uint32_t sb, int mat,
                                             uint32_t offH, uint32_t offL) {
    const uint4* srcH = reinterpret_cast<const uint4*>(g_wt_hi + (size_t)mat * HID * HID);
    const uint4* srcL = reinterpret_cast<const uint4*>(g_wt_lo + (size_t)mat * HID * HID);
#pragma unroll
    for (int it = 0; it < 4; it++) {
        int t = tid + it * GEMM_THREADS;
        int r = t >> 4;
        int c = t & 15;
        uint32_t doff = (uint32_t)(r * (PITCH * 2) + c * 16);
        cp16(sb + offH + doff, srcH + t);
        cp16(sb + offL + doff, srcL + t);
    }
}

// Load all fragments for one k-step.
__device__ __forceinline__ void load_ks(
    uint32_t sb, uint32_t offBH, uint32_t offBL,
    int wm, int wn, int ks,
    int a_lrow, int a_lsel, int b_lrow, int b_lk,
    uint32_t (*aH)[4], uint32_t (*aL)[4],
    uint32_t (*bH)[4], uint32_t (*bL)[4]) {
#pragma unroll
    for (int mi = 0; mi < 2; mi++) {
        uint32_t off = (uint32_t)(((wm * 32 + mi * 16 + a_lrow) * PITCH +
                                   ks * 16 + a_lsel * 8) * 2);
        ldsm_x4(aH[mi], sb + OFF_AH + off);
        ldsm_x4(aL[mi], sb + OFF_AL + off);
    }
#pragma unroll
    for (int np = 0; np < 2; np++) {
        uint32_t off = (uint32_t)(((wn * 32 + np * 16 + b_lrow) * PITCH +
                                   ks * 16 + b_lk) * 2);
        ldsm_x4(bH[np], sb + offBH + off);
        ldsm_x4(bL[np], sb + offBL + off);
    }
}

// Compute one mat: 16 warps, wm = wid&3 (32 rows), wn = wid>>2 (32 cols).
// k-steps register-double-buffered: ldsm for ks+1 issued before ks's MMAs.
__device__ __forceinline__ void compute_mat(
    uint32_t sb, uint32_t offBH, uint32_t offBL,
    int row0, int wm, int wn, int lane,
    float* __restrict__ out, const float* __restrict__ bias) {

    const int a_lrow = lane & 15;
    const int a_lsel = lane >> 4;
    const int b_lrow = (lane & 7) + ((lane >> 4) & 1) * 8;
    const int b_lk   = ((lane >> 3) & 1) * 8;

    float acc[2][4][4];
#pragma unroll
    for (int mi = 0; mi < 2; mi++)
#pragma unroll
        for (int ni = 0; ni < 4; ni++)
#pragma unroll
            for (int r = 0; r < 4; r++) acc[mi][ni][r] = 0.f;

    uint32_t aH[2][2][4], aL[2][2][4], bH[2][2][4], bL[2][2][4];
    load_ks(sb, offBH, offBL, wm, wn, 0, a_lrow, a_lsel, b_lrow, b_lk,
            aH[0], aL[0], bH[0], bL[0]);

#pragma unroll
    for (int ks = 0; ks < 8; ks++) {
        const int cur = ks & 1;
        const int nxt = cur ^ 1;
        if (ks < 7)
            load_ks(sb, offBH, offBL, wm, wn, ks + 1,
                    a_lrow, a_lsel, b_lrow, b_lk,
                    aH[nxt], aL[nxt], bH[nxt], bL[nxt]);
#pragma unroll
        for (int mi = 0; mi < 2; mi++)
#pragma unroll
            for (int ni = 0; ni < 4; ni++) {
                int np = ni >> 1, rb = (ni & 1) * 2;
                mma_bf16(acc[mi][ni], aH[cur][mi], bH[cur][np][rb], bH[cur][np][rb + 1]);
                mma_bf16(acc[mi][ni], aH[cur][mi], bL[cur][np][rb], bL[cur][np][rb + 1]);
                mma_bf16(acc[mi][ni], aL[cur][mi], bH[cur][np][rb], bH[cur][np][rb + 1]);
            }
    }

#pragma unroll
    for (int mi = 0; mi < 2; mi++) {
        int row = row0 + wm * 32 + mi * 16 + (lane >> 2);
#pragma unroll
        for (int ni = 0; ni < 4; ni++) {
            int col = wn * 32 + ni * 8 + (lane & 3) * 2;
            float bx = __ldg(&bias[col]);
            float by = __ldg(&bias[col + 1]);
            *reinterpret_cast<float2*>(&out[(size_t)row * HID + col]) =
                make_float2(acc[mi][ni][0] + bx, acc[mi][ni][1] + by);
            *reinterpret_cast<float2*>(&out[(size_t)(row + 8) * HID + col]) =
                make_float2(acc[mi][ni][2] + bx, acc[mi][ni][3] + by);
        }
    }
}

// ---------------------------------------------------------------------------
// GEMM: block = 128 rows x 128 cols, K=128 resident, 512 threads (16 warps),
// B tiles double-buffered via cp.async across the Q/K/V mat loop.
// ---------------------------------------------------------------------------
__global__ __launch_bounds__(GEMM_THREADS)
void qkv_gemm_wide(const float* __restrict__ h,
                   const float* __restrict__ bq, const float* __restrict__ bk,
                   const float* __restrict__ bv, int n) {
    extern __shared__ __align__(16) char smem[];
    const uint32_t sb = smem_u32(smem);
    const int tid  = threadIdx.x;
    const int wid  = tid >> 5;
    const int lane = tid & 31;
    const int wm   = wid & 3;
    const int wn   = wid >> 2;
    const int row0 = blockIdx.x * 128;

    load_B_async(tid, sb, 0, OFF_B0H, OFF_B0L);    // group 1
    CP_COMMIT();

    // Stage A: load fp32 h rows, split to bf16 hi/lo, store pitch-136.
    for (int t = tid; t < 4096; t += GEMM_THREADS) {
        int r = t >> 5;
        int c = t & 31;
        int row = row0 + r;
        float4 v = make_float4(0.f, 0.f, 0.f, 0.f);
        if (row < n)
            v = *reinterpret_cast<const float4*>(h + (size_t)row * HID + c * 4);
        float hx = __bfloat162float(__float2bfloat16_rn(v.x));
        float hy = __bfloat162float(__float2bfloat16_rn(v.y));
        float hz = __bfloat162float(__float2bfloat16_rn(v.z));
        float hw = __bfloat162float(__float2bfloat16_rn(v.w));
        uint2 phi, plo;
        phi.x = bf2_bits(v.x, v.y);
        phi.y = bf2_bits(v.z, v.w);
        plo.x = bf2_bits(v.x - hx, v.y - hy);
        plo.y = bf2_bits(v.z - hz, v.w - hw);
        uint32_t doff = (uint32_t)(r * (PITCH * 2) + c * 8);
        *reinterpret_cast<uint2*>(smem + OFF_AH + doff) = phi;
        *reinterpret_cast<uint2*>(smem + OFF_AL + doff) = plo;
    }

    load_B_async(tid, sb, 1, OFF_B1H, OFF_B1L);    // group 2
    CP_COMMIT();

    // ---- mat 0 (Q) on B0 ----
    CP_WAIT(1);              // group 1 (B0) landed
    __syncthreads();         // + A staged, all threads' copies visible
    compute_mat(sb, OFF_B0H, OFF_B0L, row0, wm, wn, lane, g_Q, bq);
    __syncthreads();         // all done reading B0

    load_B_async(tid, sb, 2, OFF_B0H, OFF_B0L);    // group 3 (reuse B0)
    CP_COMMIT();

    // ---- mat 1 (K) on B1 ----
    CP_WAIT(1);              // group 2 (B1) landed
    __syncthreads();
    compute_mat(sb, OFF_B1H, OFF_B1L, row0, wm, wn, lane, g_K, bk);

    // ---- mat 2 (V) on B0 ----
    CP_WAIT(0);              // group 3 landed
    __syncthreads();
    compute_mat(sb, OFF_B0H, OFF_B0L, row0, wm, wn, lane, g_V, bv);
}

// ---------------------------------------------------------------------------
// CSR construction by destination
// ---------------------------------------------------------------------------
__global__ void zero_kernel(int n) {
    int gid = blockIdx.x * blockDim.x + threadIdx.x;
    if (gid < n) { g_cnt[gid] = 0; g_cursor[gid] = 0; }
}

__global__ void hist_kernel(const int* __restrict__ dst, int e) {
    int gid = blockIdx.x * blockDim.x + threadIdx.x;
    if (gid < e) atomicAdd(&g_cnt[dst[gid]], 1);
}

__global__ void scan_block_kernel(int n) {
    __shared__ int sm[1024];
    int tid = threadIdx.x;
    int gid = blockIdx.x * 1024 + tid;
    int v = (gid < n) ? g_cnt[gid] : 0;
    sm[tid] = v;
    __syncthreads();
    for (int off = 1; off < 1024; off <<= 1) {
        int t = (tid >= off) ? sm[tid - off] : 0;
        __syncthreads();
        sm[tid] += t;
        __syncthreads();
    }
    if (gid < n) g_rowptr[gid] = sm[tid] - v;  // exclusive within block
    if (tid == 1023) g_blksum[blockIdx.x] = sm[1023];
}

// Parallel top-level scan over <=128 block sums (Hillis-Steele in smem).
__global__ void scan_top_kernel(int nb) {
    __shared__ int sm[128];
    int tid = threadIdx.x;
    int v = (tid < nb) ? g_blksum[tid] : 0;
    sm[tid] = v;
    __syncthreads();
    for (int off = 1; off < 128; off <<= 1) {
        int t = (tid >= off) ? sm[tid - off] : 0;
        __syncthreads();
        sm[tid] += t;
        __syncthreads();
    }
    if (tid < nb) g_blksum[tid] = sm[tid] - v;  // exclusive
}

__global__ void add_off_kernel(int n, int e) {
    int gid = blockIdx.x * blockDim.x + threadIdx.x;
    if (gid < n) g_rowptr[gid] += g_blksum[gid >> 10];
    if (gid == 0) g_rowptr[n] = e;
}

__global__ void scatter_kernel(const int* __restrict__ src,
                               const int* __restrict__ dst, int e) {
    int gid = blockIdx.x * blockDim.x + threadIdx.x;
    if (gid < e) {
        int d = dst[gid];
        int pos = g_rowptr[d] + atomicAdd(&g_cursor[d], 1);
        g_ssrc[pos] = src[gid];
    }
}

// ---------------------------------------------------------------------------
// One warp per destination node, online softmax in registers.
// ---------------------------------------------------------------------------
__global__ __launch_bounds__(256)
void attn_kernel(float* __restrict__ out, int n) {
    int gwarp = (blockIdx.x * blockDim.x + threadIdx.x) >> 5;
    if (gwarp >= n) return;
    int lane = threadIdx.x & 31;

    const float4* Q4 = reinterpret_cast<const float4*>(g_Q);
    const float4* K4 = reinterpret_cast<const float4*>(g_K);
    const float4* V4 = reinterpret_cast<const float4*>(g_V);

    float4 q = Q4[(size_t)gwarp * 32 + lane];
    int beg = g_rowptr[gwarp];
    int end = g_rowptr[gwarp + 1];

    float m = -__int_as_float(0x7f800000);  // -inf
    float s = 0.0f;
    float4 acc = make_float4(0.f, 0.f, 0.f, 0.f);

    for (int idx = beg; idx < end; idx++) {
        int sidx = __ldg(&g_ssrc[idx]);
        float4 k = K4[(size_t)sidx * 32 + lane];
        float sc = k.x * q.x + k.y * q.y + k.z * q.z + k.w * q.w;
        sc += __shfl_xor_sync(0xffffffffu, sc, 1);
        sc += __shfl_xor_sync(0xffffffffu, sc, 2);
        float mn = fmaxf(m, sc);
        float scale = __expf(m - mn);   // first iter: exp(-inf) = 0
        float p = __expf(sc - mn);
        float4 v = V4[(size_t)sidx * 32 + lane];
        s = s * scale + p;
        acc.x = acc.x * scale + p * v.x;
        acc.y = acc.y * scale + p * v.y;
        acc.z = acc.z * scale + p * v.z;
        acc.w = acc.w * scale + p * v.w;
        m = mn;
    }

    float4 o;
    if (end > beg) {
        float inv = 1.0f / s;
        o = make_float4(acc.x * inv, acc.y * inv, acc.z * inv, acc.w * inv);
    } else {
        o = make_float4(0.f, 0.f, 0.f, 0.f);
    }
    reinterpret_cast<float4*>(out)[(size_t)gwarp * 32 + lane] = o;
}

// ---------------------------------------------------------------------------
extern "C" void kernel_launch(void* const* d_in, const int* in_sizes, int n_in,
                              void* d_out, int out_size) {
    const float* h   = (const float*)d_in[0];
    const int*   src = (const int*)d_in[1];
    const int*   dst = (const int*)d_in[2];
    const float* Wq  = (const float*)d_in[3];
    const float* bq  = (const float*)d_in[4];
    const float* Wk  = (const float*)d_in[5];
    const float* bk  = (const float*)d_in[6];
    const float* Wv  = (const float*)d_in[7];
    const float* bv  = (const float*)d_in[8];
    float* out = (float*)d_out;

    int n = in_sizes[0] / HID;
    int e = in_sizes[1];

    // One-time infra (created on the uncaptured correctness call).
    static cudaStream_t s2 = nullptr;
    static cudaEvent_t ev_fork = nullptr, ev_join = nullptr;
    if (s2 == nullptr) {
        cudaStreamCreateWithFlags(&s2, cudaStreamNonBlocking);
        cudaEventCreateWithFlags(&ev_fork, cudaEventDisableTiming);
        cudaEventCreateWithFlags(&ev_join, cudaEventDisableTiming);
        cudaFuncSetAttribute(qkv_gemm_wide,
                             cudaFuncAttributeMaxDynamicSharedMemorySize,
                             GEMM_SMEM);
    }

    // Fork: CSR chain on s2, GEMM chain on the main (capture) stream.
    // Launch-call order puts qkv_gemm_wide 4th (the launch ncu captures).
    cudaEventRecord(ev_fork, 0);
    cudaStreamWaitEvent(s2, ev_fork, 0);

    zero_kernel<<<(n + 255) / 256, 256, 0, s2>>>(n);          // launch 1
    hist_kernel<<<(e + 255) / 256, 256, 0, s2>>>(dst, e);     // launch 2
    prep_w_kernel<<<(3 * HID * HID + 255) / 256, 256>>>(Wq, Wk, Wv);  // 3
    int mblocks = (n + 127) / 128;
    qkv_gemm_wide<<<mblocks, GEMM_THREADS, GEMM_SMEM>>>(h, bq, bk, bv, n); // 4

    int nb = (n + 1023) / 1024;
    scan_block_kernel<<<nb, 1024, 0, s2>>>(n);                // 5
    scan_top_kernel<<<1, 128, 0, s2>>>(nb);                   // 6
    add_off_kernel<<<(n + 255) / 256, 256, 0, s2>>>(n, e);    // 7
    scatter_kernel<<<(e + 255) / 256, 256, 0, s2>>>(src, dst, e);  // 8
    cudaEventRecord(ev_join, s2);

    // Join, then attention.
    cudaStreamWaitEvent(0, ev_join, 0);
    long long total_threads = (long long)n * 32;
    int attn_blocks = (int)((total_threads + 255) / 256);
    attn_kernel<<<attn_blocks, 256>>>(out, n);                // 9
}